// round 3
// baseline (speedup 1.0000x reference)
#include <cuda_runtime.h>
#include <math.h>

#define Bq 32
#define Vq 2048
#define Pq 64
#define Aq 8
#define Fq 72          // P + A
#define NFq 128
#define TWOF 144       // 2*F
#define VCHUNKS 16
#define VPC (Vq / VCHUNKS)   // 128

// Scratch (device globals; no allocation allowed)
__device__ float g_agg [Bq * Vq * Aq];                 // 2.1 MB
__device__ float g_M   [Bq * Aq * NFq];
__device__ float g_pmax[Bq * VCHUNKS * Aq * Fq];       // 1.18 MB
__device__ float g_psum[Bq * VCHUNKS * Aq * Fq];

typedef unsigned long long ull;

__device__ __forceinline__ void ffma2(ull& d, ull a, ull b) {
    asm("fma.rn.f32x2 %0, %1, %2, %0;" : "+l"(d) : "l"(a), "l"(b));
}
__device__ __forceinline__ ull pack2(float x) {
    ull r; asm("mov.b64 %0, {%1, %1};" : "=l"(r) : "f"(x)); return r;
}

// ---------------------------------------------------------------------------
// K1: per (b, chunk): feats = [X@W1+b1 | exp(-|X@W2+b2|)] computed into smem,
// then partial max/sum of agg[v,a]*feats[v,f] over the chunk.
// vi never goes to DRAM; agg written once (needed by K3).
// grid (VCHUNKS, B), 576 threads. GEMM map: (row=tid/9, cg=tid%9), 1x8 tile.
// Reduce map: (a=tid%8, f=tid/8).
// ---------------------------------------------------------------------------
__global__ void __launch_bounds__(576)
k1(const float* __restrict__ X,
   const float* __restrict__ W1, const float* __restrict__ b1,
   const float* __restrict__ W2, const float* __restrict__ b2) {
    extern __shared__ float sm[];
    float* Xs = sm;                 // [64][68]
    float* Ws = Xs + 64 * 68;       // [64][80]  cols 0-63: W1, 64-71: W2
    float* sf = Ws + 64 * 80;       // [64][80]  feats tile
    float* bs = sf + 64 * 80;       // [80]

    const int tid = threadIdx.x;
    const int b = blockIdx.y, ch = blockIdx.x;
    const long row0 = (long)b * Vq + (long)ch * VPC;

    for (int i = tid; i < 64 * 72; i += 576) {
        int k = i / 72, j = i % 72;
        Ws[k * 80 + j] = (j < Pq) ? W1[k * Pq + j] : W2[k * Aq + (j - Pq)];
    }
    if (tid < 72) bs[tid] = (tid < Pq) ? b1[tid] : b2[tid - Pq];

    const int row = tid / 9, cg = tid % 9;
    const int a = tid & 7, f = tid >> 3;
    float vmax = -INFINITY, vsum = 0.f;

    for (int sub = 0; sub < VPC / 64; sub++) {
        __syncthreads();   // Ws visible (iter 0); sf consumed (iters > 0)
        for (int i = tid; i < 64 * 16; i += 576) {
            int r = i >> 4, c = i & 15;
            *(float4*)(Xs + r * 68 + c * 4) =
                *(const float4*)(X + (row0 + sub * 64 + r) * Pq + c * 4);
        }
        __syncthreads();

        ull acc[4] = {0ull, 0ull, 0ull, 0ull};
#pragma unroll 4
        for (int k = 0; k < Pq; k++) {
            ull x2 = pack2(Xs[row * 68 + k]);
            const float* wr = Ws + k * 80 + cg * 8;
            ulonglong2 w01 = *(const ulonglong2*)(wr);
            ulonglong2 w23 = *(const ulonglong2*)(wr + 4);
            ffma2(acc[0], x2, w01.x);
            ffma2(acc[1], x2, w01.y);
            ffma2(acc[2], x2, w23.x);
            ffma2(acc[3], x2, w23.y);
        }
        union { ull u[4]; float f[8]; } o;
        o.u[0] = acc[0]; o.u[1] = acc[1]; o.u[2] = acc[2]; o.u[3] = acc[3];
#pragma unroll
        for (int i = 0; i < 8; i++) o.f[i] += bs[cg * 8 + i];
        if (cg == 8) {
#pragma unroll
            for (int i = 0; i < 8; i++) o.f[i] = expf(-fabsf(o.f[i]));
            float* dst = g_agg + (row0 + sub * 64 + row) * Aq;
            *(float4*)(dst)     = *(float4*)(o.f);
            *(float4*)(dst + 4) = *(float4*)(o.f + 4);
        }
        float* sdst = sf + row * 80 + cg * 8;
        *(float4*)(sdst)     = *(float4*)(o.f);
        *(float4*)(sdst + 4) = *(float4*)(o.f + 4);
        __syncthreads();

#pragma unroll 8
        for (int vv = 0; vv < 64; vv++) {
            float e = sf[vv * 80 + Pq + a];
            float p = e * sf[vv * 80 + f];
            vmax = fmaxf(vmax, p);
            vsum += p;
        }
    }
    const long o = (((long)b * VCHUNKS + ch) * Aq + a) * Fq + f;
    g_pmax[o] = vmax;
    g_psum[o] = vsum;
}

// ---------------------------------------------------------------------------
// kB2: combine partials -> collapsed[a,2F]; M[b,a,n] = collapsed @ Wout_mid + agg-direct
// ---------------------------------------------------------------------------
__global__ void kB2(const float* __restrict__ Wout) {
    const int b = blockIdx.x;
    const int tid = threadIdx.x;
    const int a = tid % Aq;
    const int f = tid / Aq;

    __shared__ float scol[Aq][TWOF];

    {
        float vmax = -INFINITY, vsum = 0.f;
        const long base = ((long)b * VCHUNKS) * Aq * Fq + a * Fq + f;
#pragma unroll
        for (int ch = 0; ch < VCHUNKS; ch++) {
            vmax = fmaxf(vmax, g_pmax[base + (long)ch * Aq * Fq]);
            vsum += g_psum[base + (long)ch * Aq * Fq];
        }
        scol[a][f]      = vmax;
        scol[a][Fq + f] = vsum * (1.0f / (float)Vq);
    }
    __syncthreads();

    for (int idx = tid; idx < Aq * NFq; idx += 576) {
        int aa = idx / NFq, n = idx % NFq;
        float acc = Wout[(Pq + Aq * TWOF + aa) * NFq + n];   // agg direct term
#pragma unroll 16
        for (int g = 0; g < TWOF; g++) {
            acc = fmaf(scol[aa][g], Wout[(Pq + aa * TWOF + g) * NFq + n], acc);
        }
        g_M[(long)b * Aq * NFq + idx] = acc;
    }
}

// ---------------------------------------------------------------------------
// K3: out = tanh( [X | agg] @ [Wout_top ; M_b] + bout )
// K=72 GEMM. BM=128 rows, BN=128 cols, 256 threads, 8x8 tile per thread.
// ---------------------------------------------------------------------------
#define BM3 128
__global__ void __launch_bounds__(256)
k3(const float* __restrict__ X, const float* __restrict__ Wout,
   const float* __restrict__ bout, float* __restrict__ out) {
    extern __shared__ float sm3[];
    float* Xs = sm3;                 // [128][72]  cols 0-63: X, 64-71: agg
    float* Ws = Xs + BM3 * Fq;       // [72][128]  rows 0-63: Wout_top, 64-71: M[b]
    float* bs = Ws + Fq * NFq;       // [128]

    const int tid = threadIdx.x;
    const long row0 = (long)blockIdx.x * BM3;
    const int b = blockIdx.x / (Vq / BM3);

    for (int i = tid; i < Fq * NFq; i += 256) {
        int k = i >> 7, j = i & 127;
        Ws[i] = (k < Pq) ? Wout[k * NFq + j]
                         : g_M[(long)b * Aq * NFq + (k - Pq) * NFq + j];
    }
    if (tid < NFq) bs[tid] = bout[tid];
    for (int i = tid; i < BM3 * 16; i += 256) {
        int r = i >> 4, c = i & 15;
        *(float4*)(Xs + r * Fq + c * 4) =
            *(const float4*)(X + (row0 + r) * Pq + c * 4);
    }
    for (int i = tid; i < BM3 * 2; i += 256) {
        int r = i >> 1, c = i & 1;
        *(float4*)(Xs + r * Fq + Pq + c * 4) =
            *(const float4*)(g_agg + (row0 + r) * Aq + c * 4);
    }
    __syncthreads();

    const int rg = tid >> 4;     // 0..15 -> rows rg*8..rg*8+7
    const int cg = tid & 15;     // 0..15 -> cols cg*8..cg*8+7

    ull acc[8][4];
#pragma unroll
    for (int r = 0; r < 8; r++)
#pragma unroll
        for (int p = 0; p < 4; p++) acc[r][p] = 0ull;

#pragma unroll 2
    for (int k = 0; k < Fq; k++) {
        const float* wr = Ws + k * NFq + cg * 8;
        ulonglong2 w01 = *(const ulonglong2*)(wr);
        ulonglong2 w23 = *(const ulonglong2*)(wr + 4);
        ull w[4] = {w01.x, w01.y, w23.x, w23.y};
        ull xd[8];
#pragma unroll
        for (int r = 0; r < 8; r++)
            xd[r] = pack2(Xs[(rg * 8 + r) * Fq + k]);
#pragma unroll
        for (int r = 0; r < 8; r++)
#pragma unroll
            for (int p = 0; p < 4; p++) ffma2(acc[r][p], xd[r], w[p]);
    }

    const int j0 = cg * 8;
    float4 bA = *(const float4*)(bs + j0);
    float4 bB = *(const float4*)(bs + j0 + 4);
#pragma unroll
    for (int r = 0; r < 8; r++) {
        const long row = row0 + rg * 8 + r;
        union { ull u; float2 f; } c0, c1, c2, c3;
        c0.u = acc[r][0]; c1.u = acc[r][1]; c2.u = acc[r][2]; c3.u = acc[r][3];
        float4 oA, oB;
        oA.x = tanhf(c0.f.x + bA.x); oA.y = tanhf(c0.f.y + bA.y);
        oA.z = tanhf(c1.f.x + bA.z); oA.w = tanhf(c1.f.y + bA.w);
        oB.x = tanhf(c2.f.x + bB.x); oB.y = tanhf(c2.f.y + bB.y);
        oB.z = tanhf(c3.f.x + bB.z); oB.w = tanhf(c3.f.y + bB.w);
        float* dst = out + row * NFq + j0;
        *(float4*)(dst)     = oA;
        *(float4*)(dst + 4) = oB;
    }
}

// ---------------------------------------------------------------------------
extern "C" void kernel_launch(void* const* d_in, const int* in_sizes, int n_in,
                              void* d_out, int out_size) {
    const float* X    = (const float*)d_in[0];
    const float* W1   = (const float*)d_in[1];
    const float* b1   = (const float*)d_in[2];
    const float* W2   = (const float*)d_in[3];
    const float* b2   = (const float*)d_in[4];
    const float* Wout = (const float*)d_in[5];
    const float* bout = (const float*)d_in[6];
    float* out = (float*)d_out;

    const int smem1 = (64 * 68 + 64 * 80 + 64 * 80 + 80) * sizeof(float);      // ~58.7 KB
    const int smem3 = (BM3 * Fq + Fq * NFq + NFq) * sizeof(float);             // ~74.2 KB
    cudaFuncSetAttribute(k1, cudaFuncAttributeMaxDynamicSharedMemorySize, smem1);
    cudaFuncSetAttribute(k3, cudaFuncAttributeMaxDynamicSharedMemorySize, smem3);

    dim3 g1(VCHUNKS, Bq);
    k1<<<g1, 576, smem1>>>(X, W1, b1, W2, b2);

    kB2<<<Bq, 576>>>(Wout);

    k3<<<(Bq * Vq) / BM3, 256, smem3>>>(X, Wout, bout, out);
}

// round 4
// speedup vs baseline: 2.0938x; 2.0938x over previous
#include <cuda_runtime.h>
#include <math.h>
#include <stdint.h>

#define Bq 32
#define Vq 2048
#define Pq 64
#define Aq 8
#define Fq 72          // P + A
#define NFq 128
#define TWOF 144       // 2*F
#define NCH 8          // V chunks for reduce kernel
#define NPC 32         // partial slots = NCH * 4 subsets

// Scratch (device globals; no allocation allowed)
__device__ float g_vi  [Bq * Vq * Pq];                 // 16.8 MB
__device__ float g_agg [Bq * Vq * Aq];                 //  2.1 MB
__device__ float g_M   [Bq * Aq * NFq];
__device__ float g_pmax[Bq * NPC * Aq * Fq];           // 2.36 MB
__device__ float g_psum[Bq * NPC * Aq * Fq];

typedef unsigned long long ull;

__device__ __forceinline__ void ffma2(ull& d, ull a, ull b) {
    asm("fma.rn.f32x2 %0, %1, %2, %0;" : "+l"(d) : "l"(a), "l"(b));
}
__device__ __forceinline__ ull pack2(float x) {
    ull r; asm("mov.b64 %0, {%1, %1};" : "=l"(r) : "f"(x)); return r;
}
__device__ __forceinline__ uint32_t f2tf32(float f) {
    uint32_t r; asm("cvt.rna.tf32.f32 %0, %1;" : "=r"(r) : "f"(f)); return r;
}
__device__ __forceinline__ void mma_tf32(float* d, const uint32_t* a, const uint32_t* b) {
    asm("mma.sync.aligned.m16n8k8.row.col.f32.tf32.tf32.f32 "
        "{%0,%1,%2,%3},{%4,%5,%6,%7},{%8,%9},{%0,%1,%2,%3};"
        : "+f"(d[0]), "+f"(d[1]), "+f"(d[2]), "+f"(d[3])
        : "r"(a[0]), "r"(a[1]), "r"(a[2]), "r"(a[3]), "r"(b[0]), "r"(b[1]));
}

// ---------------------------------------------------------------------------
// kA': vi = X@W1+b1 -> g_vi ; agg = exp(-|X@W2+b2|) -> g_agg
// BM=256 rows/block, 288 threads = 32 row-groups x 9 col-groups, 8x8 tiles.
// ---------------------------------------------------------------------------
#define AM 256
#define XTS 260        // padded Xt row stride
__global__ void __launch_bounds__(288)
kA(const float* __restrict__ X,
   const float* __restrict__ W1, const float* __restrict__ b1,
   const float* __restrict__ W2, const float* __restrict__ b2) {
    extern __shared__ float sm[];
    float* Xt = sm;                  // [64][XTS]  transposed: Xt[k][row]
    float* Ws = Xt + 64 * XTS;       // [64][80]   cols 0-63 W1, 64-71 W2
    float* bs = Ws + 64 * 80;        // [72]

    const int tid  = threadIdx.x;
    const long row0 = (long)blockIdx.x * AM;

    for (int i = tid; i < AM * 16; i += 288) {
        int r = i >> 4, kc = i & 15;
        float4 v = *(const float4*)(X + (row0 + r) * Pq + kc * 4);
        Xt[(kc * 4 + 0) * XTS + r] = v.x;
        Xt[(kc * 4 + 1) * XTS + r] = v.y;
        Xt[(kc * 4 + 2) * XTS + r] = v.z;
        Xt[(kc * 4 + 3) * XTS + r] = v.w;
    }
    for (int i = tid; i < 64 * Fq; i += 288) {
        int k = i / Fq, j = i % Fq;
        Ws[k * 80 + j] = (j < Pq) ? W1[k * Pq + j] : W2[k * Aq + (j - Pq)];
    }
    if (tid < Fq) bs[tid] = (tid < Pq) ? b1[tid] : b2[tid - Pq];
    __syncthreads();

    const int rg = tid / 9;        // 0..31 -> rows rg*8..+7
    const int cg = tid % 9;        // 0..8  -> cols cg*8..+7 (cg==8 -> agg)

    ull acc[8][4];
#pragma unroll
    for (int r = 0; r < 8; r++)
#pragma unroll
        for (int p = 0; p < 4; p++) acc[r][p] = 0ull;

#pragma unroll 4
    for (int k = 0; k < Pq; k++) {
        const float* xr = Xt + k * XTS + rg * 8;
        float4 xa = *(const float4*)(xr);
        float4 xb = *(const float4*)(xr + 4);
        const float* wr = Ws + k * 80 + cg * 8;
        ulonglong2 w01 = *(const ulonglong2*)(wr);
        ulonglong2 w23 = *(const ulonglong2*)(wr + 4);
        ull w[4] = {w01.x, w01.y, w23.x, w23.y};
        ull xd[8] = {pack2(xa.x), pack2(xa.y), pack2(xa.z), pack2(xa.w),
                     pack2(xb.x), pack2(xb.y), pack2(xb.z), pack2(xb.w)};
#pragma unroll
        for (int r = 0; r < 8; r++)
#pragma unroll
            for (int p = 0; p < 4; p++) ffma2(acc[r][p], xd[r], w[p]);
    }

    const int j0 = cg * 8;
    float4 bA = *(const float4*)(bs + j0);
    float4 bB = *(const float4*)(bs + j0 + 4);
#pragma unroll
    for (int r = 0; r < 8; r++) {
        const long row = row0 + rg * 8 + r;
        union { ull u; float2 f; } c0, c1, c2, c3;
        c0.u = acc[r][0]; c1.u = acc[r][1]; c2.u = acc[r][2]; c3.u = acc[r][3];
        float4 oA = make_float4(c0.f.x + bA.x, c0.f.y + bA.y, c1.f.x + bA.z, c1.f.y + bA.w);
        float4 oB = make_float4(c2.f.x + bB.x, c2.f.y + bB.y, c3.f.x + bB.z, c3.f.y + bB.w);
        if (cg < 8) {
            float* dst = g_vi + row * Pq + j0;
            *(float4*)(dst)     = oA;
            *(float4*)(dst + 4) = oB;
        } else {
            oA.x = expf(-fabsf(oA.x)); oA.y = expf(-fabsf(oA.y));
            oA.z = expf(-fabsf(oA.z)); oA.w = expf(-fabsf(oA.w));
            oB.x = expf(-fabsf(oB.x)); oB.y = expf(-fabsf(oB.y));
            oB.z = expf(-fabsf(oB.z)); oB.w = expf(-fabsf(oB.w));
            float* dst = g_agg + row * Aq;
            *(float4*)(dst)     = oA;
            *(float4*)(dst + 4) = oB;
        }
    }
}

// ---------------------------------------------------------------------------
// kB1: partial max/sum of agg[v,a]*feats[v,f] over V-chunks, float4 over f.
// grid (NCH, B), 576 threads: subset=tid/144 (16 v's of each 64-row tile),
// within subset: a = t%8, f4 = t/8 (18 quads = 72 f).
// ---------------------------------------------------------------------------
__global__ void __launch_bounds__(576)
kB1() {
    const int b = blockIdx.y, ch = blockIdx.x;
    const int tid = threadIdx.x;

    __shared__ float sf[64][80];

    const int sub = tid / 144;
    const int t   = tid % 144;
    const int a   = t % Aq;
    const int f4  = t / Aq;          // 0..17

    float4 vmax = make_float4(-INFINITY, -INFINITY, -INFINITY, -INFINITY);
    float4 vsum = make_float4(0.f, 0.f, 0.f, 0.f);
    const long base = (long)b * Vq + (long)ch * (Vq / NCH);

    for (int t0 = 0; t0 < (Vq / NCH); t0 += 64) {
        for (int i = tid; i < 64 * 16; i += 576) {
            int r = i >> 4, c = i & 15;
            *(float4*)&sf[r][c * 4] = *(const float4*)(g_vi + (base + t0 + r) * Pq + c * 4);
        }
        if (tid < 128) {
            int r = tid >> 1, c = tid & 1;
            *(float4*)&sf[r][Pq + c * 4] = *(const float4*)(g_agg + (base + t0 + r) * Aq + c * 4);
        }
        __syncthreads();
#pragma unroll 16
        for (int vi = 0; vi < 16; vi++) {
            const int vv = sub * 16 + vi;
            float e = sf[vv][Pq + a];
            float4 v = *(const float4*)&sf[vv][f4 * 4];
            float4 p = make_float4(e * v.x, e * v.y, e * v.z, e * v.w);
            vmax.x = fmaxf(vmax.x, p.x); vmax.y = fmaxf(vmax.y, p.y);
            vmax.z = fmaxf(vmax.z, p.z); vmax.w = fmaxf(vmax.w, p.w);
            vsum.x += p.x; vsum.y += p.y; vsum.z += p.z; vsum.w += p.w;
        }
        __syncthreads();
    }
    const int pc = ch * 4 + sub;
    const long o = (((long)b * NPC + pc) * Aq + a) * Fq + f4 * 4;
    *(float4*)(g_pmax + o) = vmax;
    *(float4*)(g_psum + o) = vsum;
}

// ---------------------------------------------------------------------------
// kB2: combine partials -> collapsed[a,2F]; M[b,a,n] = collapsed@Wout_mid + direct
// ---------------------------------------------------------------------------
__global__ void __launch_bounds__(576)
kB2(const float* __restrict__ Wout) {
    const int b = blockIdx.x;
    const int tid = threadIdx.x;
    const int a = tid % Aq;
    const int f = tid / Aq;

    __shared__ float scol[Aq][TWOF];

    {
        float vmax = -INFINITY, vsum = 0.f;
        const long base = ((long)b * NPC) * Aq * Fq + a * Fq + f;
#pragma unroll
        for (int pc = 0; pc < NPC; pc++) {
            vmax = fmaxf(vmax, g_pmax[base + (long)pc * Aq * Fq]);
            vsum += g_psum[base + (long)pc * Aq * Fq];
        }
        scol[a][f]      = vmax;
        scol[a][Fq + f] = vsum * (1.0f / (float)Vq);
    }
    __syncthreads();

    for (int idx = tid; idx < Aq * NFq; idx += 576) {
        int aa = idx / NFq, n = idx % NFq;
        float acc = Wout[(Pq + Aq * TWOF + aa) * NFq + n];   // agg direct term
#pragma unroll 16
        for (int g = 0; g < TWOF; g++) {
            acc = fmaf(scol[aa][g], Wout[(Pq + aa * TWOF + g) * NFq + n], acc);
        }
        g_M[(long)b * Aq * NFq + idx] = acc;
    }
}

// ---------------------------------------------------------------------------
// k3: out = tanh( [X | agg] @ [Wout_top ; M_b] + bout )   via tf32 mma.sync
// BM=128 rows, N=128, K=72 (9 k8 steps). 256 threads = 8 warps (2m x 4n),
// warp tile m64 x n32 = 4x4 m16n8 mma tiles.
// ---------------------------------------------------------------------------
#define K3M 128
#define XS3 76         // Xs row stride (tf32 words)
#define WS3 136        // Ws row stride
__global__ void __launch_bounds__(256)
k3(const float* __restrict__ X, const float* __restrict__ Wout,
   const float* __restrict__ bout, float* __restrict__ out) {
    extern __shared__ uint32_t sm3[];
    uint32_t* Xs = sm3;                    // [128][XS3]  cols 0-63 X, 64-71 agg
    uint32_t* Ws = Xs + K3M * XS3;         // [72][WS3]   rows 0-63 Wout_top, 64-71 M[b]
    float*    bs = (float*)(Ws + Fq * WS3);// [128]

    const int tid = threadIdx.x;
    const long row0 = (long)blockIdx.x * K3M;
    const int b = blockIdx.x / (Vq / K3M);

    // stage A = [X | agg] (convert to tf32)
    for (int i = tid; i < K3M * 16; i += 256) {
        int r = i >> 4, c = i & 15;
        float4 v = *(const float4*)(X + (row0 + r) * Pq + c * 4);
        uint32_t* d = Xs + r * XS3 + c * 4;
        d[0] = f2tf32(v.x); d[1] = f2tf32(v.y); d[2] = f2tf32(v.z); d[3] = f2tf32(v.w);
    }
    for (int i = tid; i < K3M * 2; i += 256) {
        int r = i >> 1, c = i & 1;
        float4 v = *(const float4*)(g_agg + (row0 + r) * Aq + c * 4);
        uint32_t* d = Xs + r * XS3 + Pq + c * 4;
        d[0] = f2tf32(v.x); d[1] = f2tf32(v.y); d[2] = f2tf32(v.z); d[3] = f2tf32(v.w);
    }
    // stage B = [Wout_top ; M_b]
    for (int i = tid; i < Fq * 32; i += 256) {
        int k = i >> 5, j = (i & 31) * 4;
        float4 v;
        if (k < Pq) v = *(const float4*)(Wout + k * NFq + j);
        else        v = *(const float4*)(g_M + (long)b * Aq * NFq + (k - Pq) * NFq + j);
        uint32_t* d = Ws + k * WS3 + j;
        d[0] = f2tf32(v.x); d[1] = f2tf32(v.y); d[2] = f2tf32(v.z); d[3] = f2tf32(v.w);
    }
    if (tid < NFq) bs[tid] = bout[tid];
    __syncthreads();

    const int wid = tid >> 5, lane = tid & 31;
    const int wm = wid >> 2, wn = wid & 3;
    const int lq = lane & 3, lg = lane >> 2;

    float d[4][4][4];
#pragma unroll
    for (int mt = 0; mt < 4; mt++)
#pragma unroll
        for (int nt = 0; nt < 4; nt++)
#pragma unroll
            for (int r = 0; r < 4; r++) d[mt][nt][r] = 0.f;

    for (int ks = 0; ks < 9; ks++) {
        const int k0 = ks * 8;
        uint32_t a[4][4];
#pragma unroll
        for (int mt = 0; mt < 4; mt++) {
            const int mr = wm * 64 + mt * 16 + lg;
            a[mt][0] = Xs[(mr)     * XS3 + k0 + lq];
            a[mt][1] = Xs[(mr + 8) * XS3 + k0 + lq];
            a[mt][2] = Xs[(mr)     * XS3 + k0 + 4 + lq];
            a[mt][3] = Xs[(mr + 8) * XS3 + k0 + 4 + lq];
        }
        uint32_t bfr[4][2];
#pragma unroll
        for (int nt = 0; nt < 4; nt++) {
            const int nc = wn * 32 + nt * 8 + lg;
            bfr[nt][0] = Ws[(k0 + lq)     * WS3 + nc];
            bfr[nt][1] = Ws[(k0 + 4 + lq) * WS3 + nc];
        }
#pragma unroll
        for (int mt = 0; mt < 4; mt++)
#pragma unroll
            for (int nt = 0; nt < 4; nt++)
                mma_tf32(d[mt][nt], a[mt], bfr[nt]);
    }

    // epilogue: bias + tanh, float2 stores
#pragma unroll
    for (int mt = 0; mt < 4; mt++) {
        const long r0 = row0 + wm * 64 + mt * 16 + lg;
#pragma unroll
        for (int nt = 0; nt < 4; nt++) {
            const int c0 = wn * 32 + nt * 8 + 2 * lq;
            float2 o0, o1;
            o0.x = tanhf(d[mt][nt][0] + bs[c0]);
            o0.y = tanhf(d[mt][nt][1] + bs[c0 + 1]);
            o1.x = tanhf(d[mt][nt][2] + bs[c0]);
            o1.y = tanhf(d[mt][nt][3] + bs[c0 + 1]);
            *(float2*)(out + (r0)     * NFq + c0) = o0;
            *(float2*)(out + (r0 + 8) * NFq + c0) = o1;
        }
    }
}

// ---------------------------------------------------------------------------
extern "C" void kernel_launch(void* const* d_in, const int* in_sizes, int n_in,
                              void* d_out, int out_size) {
    const float* X    = (const float*)d_in[0];
    const float* W1   = (const float*)d_in[1];
    const float* b1   = (const float*)d_in[2];
    const float* W2   = (const float*)d_in[3];
    const float* b2   = (const float*)d_in[4];
    const float* Wout = (const float*)d_in[5];
    const float* bout = (const float*)d_in[6];
    float* out = (float*)d_out;

    const int smemA = (64 * XTS + 64 * 80 + 80) * sizeof(float);            // ~87.4 KB
    const int smem3 = (K3M * XS3 + Fq * WS3 + NFq) * sizeof(uint32_t);      // ~78.6 KB
    cudaFuncSetAttribute(kA, cudaFuncAttributeMaxDynamicSharedMemorySize, smemA);
    cudaFuncSetAttribute(k3, cudaFuncAttributeMaxDynamicSharedMemorySize, smem3);

    kA<<<(Bq * Vq) / AM, 288, smemA>>>(X, W1, b1, W2, b2);

    dim3 g1(NCH, Bq);
    kB1<<<g1, 576>>>();

    kB2<<<Bq, 576>>>(Wout);

    k3<<<(Bq * Vq) / K3M, 256, smem3>>>(X, Wout, bout, out);
}

// round 5
// speedup vs baseline: 3.0393x; 1.4516x over previous
#include <cuda_runtime.h>
#include <math.h>
#include <stdint.h>

#define Bq 32
#define Vq 2048
#define Pq 64
#define Aq 8
#define Fq 72          // P + A
#define NFq 128
#define TWOF 144       // 2*F
#define NPC 16         // partial slots per batch (= V/128)

// Scratch (device globals; no allocation allowed)
__device__ float g_agg [Bq * Vq * Aq];                 // 2.1 MB
__device__ float g_M   [Bq * Aq * NFq];
__device__ float g_pmax[Bq * NPC * Aq * Fq];
__device__ float g_psum[Bq * NPC * Aq * Fq];

__device__ __forceinline__ uint32_t f2tf32(float f) {
    uint32_t r; asm("cvt.rna.tf32.f32 %0, %1;" : "=r"(r) : "f"(f)); return r;
}
__device__ __forceinline__ void mma_tf32(float* d, const uint32_t* a, const uint32_t* b) {
    asm("mma.sync.aligned.m16n8k8.row.col.f32.tf32.tf32.f32 "
        "{%0,%1,%2,%3},{%4,%5,%6,%7},{%8,%9},{%0,%1,%2,%3};"
        : "+f"(d[0]), "+f"(d[1]), "+f"(d[2]), "+f"(d[3])
        : "r"(a[0]), "r"(a[1]), "r"(a[2]), "r"(a[3]), "r"(b[0]), "r"(b[1]));
}
__device__ __forceinline__ uint32_t s2u(const void* p) {
    return (uint32_t)__cvta_generic_to_shared(p);
}
__device__ __forceinline__ void ldsm4(uint32_t* r, uint32_t addr) {
    asm volatile("ldmatrix.sync.aligned.m8n8.x4.shared.b16 {%0,%1,%2,%3}, [%4];"
                 : "=r"(r[0]), "=r"(r[1]), "=r"(r[2]), "=r"(r[3]) : "r"(addr));
}
__device__ __forceinline__ void ldsm2(uint32_t* r, uint32_t addr) {
    asm volatile("ldmatrix.sync.aligned.m8n8.x2.shared.b16 {%0,%1}, [%2];"
                 : "=r"(r[0]), "=r"(r[1]) : "r"(addr));
}
__device__ __forceinline__ float ftanh(float x) {
    float e = __expf(2.0f * x);
    return 1.0f - __fdividef(2.0f, e + 1.0f);
}

// ---------------------------------------------------------------------------
// k1: per 128-row tile: feats = [X@W1+b1 | exp(-|X@W2+b2|)] via tf32 MMA into
// smem; agg also to global; then partial max/sum of agg[v,a]*feats[v,f].
// 256 threads = 8 warps, warp w owns rows w*16..w*16+15, all 9 n-tiles.
// ---------------------------------------------------------------------------
#define XS1 68         // tf32 word stride of Xs / Wt rows
#define SFS 80         // float stride of feats tile
__global__ void __launch_bounds__(256)
k1(const float* __restrict__ X,
   const float* __restrict__ W1, const float* __restrict__ b1,
   const float* __restrict__ W2, const float* __restrict__ b2) {
    extern __shared__ uint32_t smu[];
    uint32_t* Xs = smu;                   // [128][68] tf32, rows=v, cols=k
    uint32_t* Wt = Xs + 128 * XS1;        // [72][68]  tf32, rows=n, cols=k
    float*    sf = (float*)(Wt + Fq * XS1);  // [128][80] feats
    float*    bs = sf + 128 * SFS;        // [72]

    const int tid = threadIdx.x;
    const long row0 = (long)blockIdx.x * 128;
    const int b = blockIdx.x >> 4, chunk = blockIdx.x & 15;

    for (int i = tid; i < 128 * 16; i += 256) {
        int r = i >> 4, c = i & 15;
        float4 v = *(const float4*)(X + (row0 + r) * Pq + c * 4);
        uint32_t* d = Xs + r * XS1 + c * 4;
        d[0] = f2tf32(v.x); d[1] = f2tf32(v.y); d[2] = f2tf32(v.z); d[3] = f2tf32(v.w);
    }
    for (int i = tid; i < 64 * 64; i += 256) {      // Wt[n][k] = W1[k][n]
        int k = i >> 6, n = i & 63;
        Wt[n * XS1 + k] = f2tf32(W1[i]);
    }
    for (int i = tid; i < 64 * 8; i += 256) {       // Wt[64+n][k] = W2[k][n]
        int k = i >> 3, n = i & 7;
        Wt[(64 + n) * XS1 + k] = f2tf32(W2[i]);
    }
    if (tid < Fq) bs[tid] = (tid < Pq) ? b1[tid] : b2[tid - Pq];
    __syncthreads();

    const int wid = tid >> 5, lane = tid & 31;
    const int lq = lane & 3, lg = lane >> 2;

    // ldmatrix lane address offsets
    const int rA = lane & 15;                   // A row within warp tile
    const int cA = (lane & 16) >> 2;            // A col k-offset (words)
    const int rB = (lane & 7) + ((lane & 16) >> 1);
    const int cB = (lane & 8) >> 1;

    uint32_t aAddr = s2u(Xs + (wid * 16 + rA) * XS1 + cA);
    uint32_t bAddrP[4];
#pragma unroll
    for (int p = 0; p < 4; p++)
        bAddrP[p] = s2u(Wt + (p * 16 + rB) * XS1 + cB);
    uint32_t bAddr2 = s2u(Wt + (64 + (lane & 7)) * XS1 + cB);

    float d[9][4];
#pragma unroll
    for (int nt = 0; nt < 9; nt++)
#pragma unroll
        for (int r = 0; r < 4; r++) d[nt][r] = 0.f;

#pragma unroll
    for (int ks = 0; ks < 8; ks++) {
        uint32_t a[4];
        ldsm4(a, aAddr); aAddr += 32;
        uint32_t bf[9][2];
#pragma unroll
        for (int p = 0; p < 4; p++) {
            ldsm4(&bf[2 * p][0], bAddrP[p]); bAddrP[p] += 32;
        }
        ldsm2(bf[8], bAddr2); bAddr2 += 32;
#pragma unroll
        for (int nt = 0; nt < 9; nt++) mma_tf32(d[nt], a, bf[nt]);
    }

    const int orow = wid * 16 + lg;
#pragma unroll
    for (int nt = 0; nt < 8; nt++) {
        const int col = nt * 8 + 2 * lq;
        float2 lo = make_float2(d[nt][0] + bs[col], d[nt][1] + bs[col + 1]);
        float2 hi = make_float2(d[nt][2] + bs[col], d[nt][3] + bs[col + 1]);
        *(float2*)&sf[orow * SFS + col]       = lo;
        *(float2*)&sf[(orow + 8) * SFS + col] = hi;
    }
    {   // agg tile (nt = 8)
        const int col = 64 + 2 * lq;
        float e0 = __expf(-fabsf(d[8][0] + bs[col]));
        float e1 = __expf(-fabsf(d[8][1] + bs[col + 1]));
        float e2 = __expf(-fabsf(d[8][2] + bs[col]));
        float e3 = __expf(-fabsf(d[8][3] + bs[col + 1]));
        *(float2*)&sf[orow * SFS + col]       = make_float2(e0, e1);
        *(float2*)&sf[(orow + 8) * SFS + col] = make_float2(e2, e3);
        *(float2*)(g_agg + (row0 + orow) * Aq + 2 * lq)     = make_float2(e0, e1);
        *(float2*)(g_agg + (row0 + orow + 8) * Aq + 2 * lq) = make_float2(e2, e3);
    }
    __syncthreads();

    // partial reduce over the 128 rows: prod[a,v,f] = agg[v,a]*feats[v,f]
    const int a8  = tid & 7;
    const int f2i = tid >> 3;      // float2 index 0..31 (f cols 0..63)
    {
        float2 mx = make_float2(-INFINITY, -INFINITY);
        float2 sm = make_float2(0.f, 0.f);
#pragma unroll 4
        for (int v = 0; v < 128; v++) {
            float e = sf[v * SFS + 64 + a8];
            float2 x = *(float2*)&sf[v * SFS + 2 * f2i];
            float px = e * x.x, py = e * x.y;
            mx.x = fmaxf(mx.x, px); mx.y = fmaxf(mx.y, py);
            sm.x += px; sm.y += py;
        }
        const long o = (((long)b * NPC + chunk) * Aq + a8) * Fq + 2 * f2i;
        *(float2*)(g_pmax + o) = mx;
        *(float2*)(g_psum + o) = sm;
    }
    if (f2i < 4) {   // f cols 64..71 (pairs 32..35)
        float2 mx = make_float2(-INFINITY, -INFINITY);
        float2 sm = make_float2(0.f, 0.f);
#pragma unroll 4
        for (int v = 0; v < 128; v++) {
            float e = sf[v * SFS + 64 + a8];
            float2 x = *(float2*)&sf[v * SFS + 64 + 2 * f2i];
            float px = e * x.x, py = e * x.y;
            mx.x = fmaxf(mx.x, px); mx.y = fmaxf(mx.y, py);
            sm.x += px; sm.y += py;
        }
        const long o = (((long)b * NPC + chunk) * Aq + a8) * Fq + 2 * (f2i + 32);
        *(float2*)(g_pmax + o) = mx;
        *(float2*)(g_psum + o) = sm;
    }
}

// ---------------------------------------------------------------------------
// kB2: combine partials -> collapsed[a,2F]; M[b,a,n] = collapsed@Wout_mid + direct
// ---------------------------------------------------------------------------
__global__ void __launch_bounds__(576)
kB2(const float* __restrict__ Wout) {
    const int b = blockIdx.x;
    const int tid = threadIdx.x;
    const int a = tid % Aq;
    const int f = tid / Aq;

    __shared__ float scol[Aq][TWOF];

    {
        float vmax = -INFINITY, vsum = 0.f;
        const long base = ((long)b * NPC) * Aq * Fq + a * Fq + f;
#pragma unroll
        for (int pc = 0; pc < NPC; pc++) {
            vmax = fmaxf(vmax, g_pmax[base + (long)pc * Aq * Fq]);
            vsum += g_psum[base + (long)pc * Aq * Fq];
        }
        scol[a][f]      = vmax;
        scol[a][Fq + f] = vsum * (1.0f / (float)Vq);
    }
    __syncthreads();

    for (int idx = tid; idx < Aq * NFq; idx += 576) {
        int aa = idx / NFq, n = idx % NFq;
        float acc = Wout[(Pq + Aq * TWOF + aa) * NFq + n];   // agg direct term
#pragma unroll 16
        for (int g = 0; g < TWOF; g++) {
            acc = fmaf(scol[aa][g], Wout[(Pq + aa * TWOF + g) * NFq + n], acc);
        }
        g_M[(long)b * Aq * NFq + idx] = acc;
    }
}

// ---------------------------------------------------------------------------
// k3: out = tanh( [X | agg] @ [Wout_top ; M_b] + bout ) via tf32 MMA + ldmatrix
// BM=128, N=128, K=72. 8 warps (2m x 4n), warp m64 x n32.
// ---------------------------------------------------------------------------
#define XS3 76
__global__ void __launch_bounds__(256)
k3(const float* __restrict__ X, const float* __restrict__ Wout,
   const float* __restrict__ bout, float* __restrict__ out) {
    extern __shared__ uint32_t sm3[];
    uint32_t* Xs = sm3;                   // [128][76] tf32: cols 0-63 X, 64-71 agg
    uint32_t* Wt = Xs + 128 * XS3;        // [128][76] tf32: rows n, cols k (0..71)
    float*    bs = (float*)(Wt + 128 * XS3);  // [128]

    const int tid = threadIdx.x;
    const long row0 = (long)blockIdx.x * 128;
    const int b = blockIdx.x >> 4;

    for (int i = tid; i < 128 * 16; i += 256) {
        int r = i >> 4, c = i & 15;
        float4 v = *(const float4*)(X + (row0 + r) * Pq + c * 4);
        uint32_t* d = Xs + r * XS3 + c * 4;
        d[0] = f2tf32(v.x); d[1] = f2tf32(v.y); d[2] = f2tf32(v.z); d[3] = f2tf32(v.w);
    }
    for (int i = tid; i < 128 * 2; i += 256) {
        int r = i >> 1, c = i & 1;
        float4 v = *(const float4*)(g_agg + (row0 + r) * Aq + c * 4);
        uint32_t* d = Xs + r * XS3 + Pq + c * 4;
        d[0] = f2tf32(v.x); d[1] = f2tf32(v.y); d[2] = f2tf32(v.z); d[3] = f2tf32(v.w);
    }
    for (int i = tid; i < Fq * NFq; i += 256) {   // Wt[n][k]
        int k = i >> 7, n = i & 127;
        float v = (k < Pq) ? Wout[k * NFq + n]
                           : g_M[(long)b * Aq * NFq + (k - Pq) * NFq + n];
        Wt[n * XS3 + k] = f2tf32(v);
    }
    if (tid < NFq) bs[tid] = bout[tid];
    __syncthreads();

    const int wid = tid >> 5, lane = tid & 31;
    const int wm = wid >> 2, wn = wid & 3;
    const int lq = lane & 3, lg = lane >> 2;

    const int rA = lane & 15;
    const int cA = (lane & 16) >> 2;
    const int rB = (lane & 7) + ((lane & 16) >> 1);
    const int cB = (lane & 8) >> 1;

    uint32_t aAddr[4], bAddr[2];
#pragma unroll
    for (int mt = 0; mt < 4; mt++)
        aAddr[mt] = s2u(Xs + (wm * 64 + mt * 16 + rA) * XS3 + cA);
#pragma unroll
    for (int p = 0; p < 2; p++)
        bAddr[p] = s2u(Wt + (wn * 32 + p * 16 + rB) * XS3 + cB);

    float d[4][4][4];
#pragma unroll
    for (int mt = 0; mt < 4; mt++)
#pragma unroll
        for (int nt = 0; nt < 4; nt++)
#pragma unroll
            for (int r = 0; r < 4; r++) d[mt][nt][r] = 0.f;

#pragma unroll
    for (int ks = 0; ks < 9; ks++) {
        uint32_t a[4][4];
#pragma unroll
        for (int mt = 0; mt < 4; mt++) {
            ldsm4(a[mt], aAddr[mt]); aAddr[mt] += 32;
        }
        uint32_t bf[4][2];
#pragma unroll
        for (int p = 0; p < 2; p++) {
            ldsm4(&bf[2 * p][0], bAddr[p]); bAddr[p] += 32;
        }
#pragma unroll
        for (int mt = 0; mt < 4; mt++)
#pragma unroll
            for (int nt = 0; nt < 4; nt++)
                mma_tf32(d[mt][nt], a[mt], bf[nt]);
    }

#pragma unroll
    for (int mt = 0; mt < 4; mt++) {
        const long r0 = row0 + wm * 64 + mt * 16 + lg;
#pragma unroll
        for (int nt = 0; nt < 4; nt++) {
            const int c0 = wn * 32 + nt * 8 + 2 * lq;
            float2 o0, o1;
            o0.x = ftanh(d[mt][nt][0] + bs[c0]);
            o0.y = ftanh(d[mt][nt][1] + bs[c0 + 1]);
            o1.x = ftanh(d[mt][nt][2] + bs[c0]);
            o1.y = ftanh(d[mt][nt][3] + bs[c0 + 1]);
            *(float2*)(out + (r0)     * NFq + c0) = o0;
            *(float2*)(out + (r0 + 8) * NFq + c0) = o1;
        }
    }
}

// ---------------------------------------------------------------------------
extern "C" void kernel_launch(void* const* d_in, const int* in_sizes, int n_in,
                              void* d_out, int out_size) {
    const float* X    = (const float*)d_in[0];
    const float* W1   = (const float*)d_in[1];
    const float* b1   = (const float*)d_in[2];
    const float* W2   = (const float*)d_in[3];
    const float* b2   = (const float*)d_in[4];
    const float* Wout = (const float*)d_in[5];
    const float* bout = (const float*)d_in[6];
    float* out = (float*)d_out;

    const int smem1 = (128 * XS1 + Fq * XS1) * 4 + 128 * SFS * 4 + Fq * 4;   // ~95.6 KB
    const int smem3 = (128 * XS3 * 2) * 4 + NFq * 4;                          // ~78.3 KB
    cudaFuncSetAttribute(k1, cudaFuncAttributeMaxDynamicSharedMemorySize, smem1);
    cudaFuncSetAttribute(k3, cudaFuncAttributeMaxDynamicSharedMemorySize, smem3);

    k1<<<(Bq * Vq) / 128, 256, smem1>>>(X, W1, b1, W2, b2);

    kB2<<<Bq, 576>>>(Wout);

    k3<<<(Bq * Vq) / 128, 256, smem3>>>(X, Wout, bout, out);
}

// round 6
// speedup vs baseline: 3.2710x; 1.0762x over previous
#include <cuda_runtime.h>
#include <math.h>
#include <stdint.h>

#define Bq 32
#define Vq 2048
#define Pq 64
#define Aq 8
#define Fq 72          // P + A
#define NFq 128
#define TWOF 144       // 2*F
#define NPC 32         // partial slots per batch (= V/128 chunks * 2 subsets)

// Scratch (device globals; no allocation allowed)
__device__ float g_agg [Bq * Vq * Aq];                 // 2.1 MB
__device__ float g_M   [Bq * Aq * NFq];
__device__ float g_pmax[Bq * NPC * Aq * Fq];
__device__ float g_psum[Bq * NPC * Aq * Fq];

__device__ __forceinline__ uint32_t f2tf32(float f) {
    uint32_t r; asm("cvt.rna.tf32.f32 %0, %1;" : "=r"(r) : "f"(f)); return r;
}
__device__ __forceinline__ void mma_tf32(float* d, const uint32_t* a, const uint32_t* b) {
    asm("mma.sync.aligned.m16n8k8.row.col.f32.tf32.tf32.f32 "
        "{%0,%1,%2,%3},{%4,%5,%6,%7},{%8,%9},{%0,%1,%2,%3};"
        : "+f"(d[0]), "+f"(d[1]), "+f"(d[2]), "+f"(d[3])
        : "r"(a[0]), "r"(a[1]), "r"(a[2]), "r"(a[3]), "r"(b[0]), "r"(b[1]));
}
__device__ __forceinline__ uint32_t s2u(const void* p) {
    return (uint32_t)__cvta_generic_to_shared(p);
}
__device__ __forceinline__ void ldsm4(uint32_t* r, uint32_t addr) {
    asm volatile("ldmatrix.sync.aligned.m8n8.x4.shared.b16 {%0,%1,%2,%3}, [%4];"
                 : "=r"(r[0]), "=r"(r[1]), "=r"(r[2]), "=r"(r[3]) : "r"(addr));
}
__device__ __forceinline__ void ldsm2(uint32_t* r, uint32_t addr) {
    asm volatile("ldmatrix.sync.aligned.m8n8.x2.shared.b16 {%0,%1}, [%2];"
                 : "=r"(r[0]), "=r"(r[1]) : "r"(addr));
}
__device__ __forceinline__ float ftanh(float x) {
    float e = __expf(2.0f * x);
    return 1.0f - __fdividef(2.0f, e + 1.0f);
}

// ---------------------------------------------------------------------------
// k1: per 128-row tile: feats = [X@W1+b1 | exp(-|X@W2+b2|)] via tf32 MMA into
// smem (aliased over Xs), then 2-subset partial max/sum of agg[v,a]*feats[v,f].
// 576 threads = 18 warps. MMA: warps 0-15 (8 row-groups x 2 n-groups).
// Reduce: 2 v-subsets x (8 a x 36 f2).
// ---------------------------------------------------------------------------
#define XS1 68         // tf32 word stride of Xs / Wt rows
#define SFS 80         // float stride of feats tile
__global__ void __launch_bounds__(576)
k1(const float* __restrict__ X,
   const float* __restrict__ W1, const float* __restrict__ b1,
   const float* __restrict__ W2, const float* __restrict__ b2) {
    extern __shared__ uint32_t smu[];
    uint32_t* Wt = smu;                     // [72][68] tf32, rows=n, cols=k
    uint32_t* Xs = Wt + Fq * XS1;           // [128][68] tf32 (aliased with sf)
    float*    sf = (float*)Xs;              // [128][80] feats (after MMA)
    float*    bs = (float*)(Xs + 128 * SFS);// [72]  (sf is the larger layout)

    const int tid = threadIdx.x;
    const long row0 = (long)blockIdx.x * 128;
    const int b = blockIdx.x >> 4, chunk = blockIdx.x & 15;

    for (int i = tid; i < 128 * 16; i += 576) {
        int r = i >> 4, c = i & 15;
        float4 v = *(const float4*)(X + (row0 + r) * Pq + c * 4);
        uint32_t* d = Xs + r * XS1 + c * 4;
        d[0] = f2tf32(v.x); d[1] = f2tf32(v.y); d[2] = f2tf32(v.z); d[3] = f2tf32(v.w);
    }
    for (int i = tid; i < 64 * 64; i += 576) {      // Wt[n][k] = W1[k][n]
        int k = i >> 6, n = i & 63;
        Wt[n * XS1 + k] = f2tf32(W1[i]);
    }
    for (int i = tid; i < 64 * 8; i += 576) {       // Wt[64+n][k] = W2[k][n]
        int k = i >> 3, n = i & 7;
        Wt[(64 + n) * XS1 + k] = f2tf32(W2[i]);
    }
    if (tid < Fq) bs[tid] = (tid < Pq) ? b1[tid] : b2[tid - Pq];
    __syncthreads();

    const int wid = tid >> 5, lane = tid & 31;
    const int lq = lane & 3, lg = lane >> 2;

    float d[5][4];
    int rg = 0, wg = 0;

    if (wid < 16) {
        rg = wid & 7;            // row group: rows rg*16..+15
        wg = wid >> 3;           // n group: 0 -> nt 0..4, 1 -> nt 5..8

        const int rA = lane & 15;
        const int cA = (lane & 16) >> 2;
        const int rB = (lane & 7) + ((lane & 16) >> 1);
        const int cB = (lane & 8) >> 1;

        uint32_t aAddr = s2u(Xs + (rg * 16 + rA) * XS1 + cA);

#pragma unroll
        for (int nt = 0; nt < 5; nt++)
#pragma unroll
            for (int r = 0; r < 4; r++) d[nt][r] = 0.f;

        if (wg == 0) {
            uint32_t b0 = s2u(Wt + (0  + rB) * XS1 + cB);
            uint32_t b1a = s2u(Wt + (16 + rB) * XS1 + cB);
            uint32_t b2a = s2u(Wt + (32 + (lane & 7)) * XS1 + cB);
#pragma unroll
            for (int ks = 0; ks < 8; ks++) {
                uint32_t a[4];
                ldsm4(a, aAddr); aAddr += 32;
                uint32_t bf[5][2];
                ldsm4(&bf[0][0], b0);  b0  += 32;
                ldsm4(&bf[2][0], b1a); b1a += 32;
                ldsm2(bf[4], b2a);     b2a += 32;
#pragma unroll
                for (int nt = 0; nt < 5; nt++) mma_tf32(d[nt], a, bf[nt]);
            }
        } else {
            uint32_t b0 = s2u(Wt + (40 + rB) * XS1 + cB);
            uint32_t b1a = s2u(Wt + (56 + rB) * XS1 + cB);
#pragma unroll
            for (int ks = 0; ks < 8; ks++) {
                uint32_t a[4];
                ldsm4(a, aAddr); aAddr += 32;
                uint32_t bf[4][2];
                ldsm4(&bf[0][0], b0);  b0  += 32;
                ldsm4(&bf[2][0], b1a); b1a += 32;
#pragma unroll
                for (int nt = 0; nt < 4; nt++) mma_tf32(d[nt], a, bf[nt]);
            }
        }
    }
    __syncthreads();   // all Xs reads done; safe to overwrite with sf

    if (wid < 16) {
        const int orow = rg * 16 + lg;
        if (wg == 0) {
#pragma unroll
            for (int nt = 0; nt < 5; nt++) {
                const int col = nt * 8 + 2 * lq;
                *(float2*)&sf[orow * SFS + col] =
                    make_float2(d[nt][0] + bs[col], d[nt][1] + bs[col + 1]);
                *(float2*)&sf[(orow + 8) * SFS + col] =
                    make_float2(d[nt][2] + bs[col], d[nt][3] + bs[col + 1]);
            }
        } else {
#pragma unroll
            for (int nt = 0; nt < 3; nt++) {
                const int col = (nt + 5) * 8 + 2 * lq;
                *(float2*)&sf[orow * SFS + col] =
                    make_float2(d[nt][0] + bs[col], d[nt][1] + bs[col + 1]);
                *(float2*)&sf[(orow + 8) * SFS + col] =
                    make_float2(d[nt][2] + bs[col], d[nt][3] + bs[col + 1]);
            }
            {   // nt local 3 = global 8 -> agg cols 64..71
                const int col = 64 + 2 * lq;
                float e0 = __expf(-fabsf(d[3][0] + bs[col]));
                float e1 = __expf(-fabsf(d[3][1] + bs[col + 1]));
                float e2 = __expf(-fabsf(d[3][2] + bs[col]));
                float e3 = __expf(-fabsf(d[3][3] + bs[col + 1]));
                *(float2*)&sf[orow * SFS + col]       = make_float2(e0, e1);
                *(float2*)&sf[(orow + 8) * SFS + col] = make_float2(e2, e3);
                *(float2*)(g_agg + (row0 + orow) * Aq + 2 * lq)     = make_float2(e0, e1);
                *(float2*)(g_agg + (row0 + orow + 8) * Aq + 2 * lq) = make_float2(e2, e3);
            }
        }
    }
    __syncthreads();

    // partial reduce: 2 subsets of 64 v each; thread -> (a, f2 pair)
    {
        const int sub = tid / 288;
        const int t   = tid % 288;
        const int a8  = t & 7;
        const int f2i = t >> 3;          // 0..35 -> f cols 2*f2i, 2*f2i+1
        const int vbase = sub * 64;

        float2 mx = make_float2(-INFINITY, -INFINITY);
        float2 smv = make_float2(0.f, 0.f);
#pragma unroll 8
        for (int i = 0; i < 64; i++) {
            const int v = vbase + i;
            float e = sf[v * SFS + 64 + a8];
            float2 x = *(float2*)&sf[v * SFS + 2 * f2i];
            float px = e * x.x, py = e * x.y;
            mx.x = fmaxf(mx.x, px); mx.y = fmaxf(mx.y, py);
            smv.x += px; smv.y += py;
        }
        const int pc = chunk * 2 + sub;
        const long o = (((long)b * NPC + pc) * Aq + a8) * Fq + 2 * f2i;
        *(float2*)(g_pmax + o) = mx;
        *(float2*)(g_psum + o) = smv;
    }
}

// ---------------------------------------------------------------------------
// kB2: combine partials -> collapsed[a,2F]; M[b,a,n] = collapsed@Wout_mid + direct
// ---------------------------------------------------------------------------
__global__ void __launch_bounds__(576)
kB2(const float* __restrict__ Wout) {
    const int b = blockIdx.x;
    const int tid = threadIdx.x;
    const int a = tid % Aq;
    const int f = tid / Aq;

    __shared__ float scol[Aq][TWOF];

    {
        float vmax = -INFINITY, vsum = 0.f;
        const long base = ((long)b * NPC) * Aq * Fq + a * Fq + f;
#pragma unroll
        for (int pc = 0; pc < NPC; pc++) {
            vmax = fmaxf(vmax, g_pmax[base + (long)pc * Aq * Fq]);
            vsum += g_psum[base + (long)pc * Aq * Fq];
        }
        scol[a][f]      = vmax;
        scol[a][Fq + f] = vsum * (1.0f / (float)Vq);
    }
    __syncthreads();

    for (int idx = tid; idx < Aq * NFq; idx += 576) {
        int aa = idx / NFq, n = idx % NFq;
        float acc = Wout[(Pq + Aq * TWOF + aa) * NFq + n];   // agg direct term
#pragma unroll 16
        for (int g = 0; g < TWOF; g++) {
            acc = fmaf(scol[aa][g], Wout[(Pq + aa * TWOF + g) * NFq + n], acc);
        }
        g_M[(long)b * Aq * NFq + idx] = acc;
    }
}

// ---------------------------------------------------------------------------
// k3: out = tanh( [X | agg] @ [Wout_top ; M_b] + bout ) via tf32 MMA + ldmatrix
// BM=128, N=128, K=72. 512 threads = 16 warps (4m x 4n), warp tile m32 x n32.
// ---------------------------------------------------------------------------
#define XS3 76
__global__ void __launch_bounds__(512)
k3(const float* __restrict__ X, const float* __restrict__ Wout,
   const float* __restrict__ bout, float* __restrict__ out) {
    extern __shared__ uint32_t sm3[];
    uint32_t* Xs = sm3;                   // [128][76] tf32: cols 0-63 X, 64-71 agg
    uint32_t* Wt = Xs + 128 * XS3;        // [128][76] tf32: rows n, cols k (0..71)
    float*    bs = (float*)(Wt + 128 * XS3);  // [128]

    const int tid = threadIdx.x;
    const long row0 = (long)blockIdx.x * 128;
    const int b = blockIdx.x >> 4;

    for (int i = tid; i < 128 * 16; i += 512) {
        int r = i >> 4, c = i & 15;
        float4 v = *(const float4*)(X + (row0 + r) * Pq + c * 4);
        uint32_t* d = Xs + r * XS3 + c * 4;
        d[0] = f2tf32(v.x); d[1] = f2tf32(v.y); d[2] = f2tf32(v.z); d[3] = f2tf32(v.w);
    }
    for (int i = tid; i < 128 * 2; i += 512) {
        int r = i >> 1, c = i & 1;
        float4 v = *(const float4*)(g_agg + (row0 + r) * Aq + c * 4);
        uint32_t* d = Xs + r * XS3 + Pq + c * 4;
        d[0] = f2tf32(v.x); d[1] = f2tf32(v.y); d[2] = f2tf32(v.z); d[3] = f2tf32(v.w);
    }
    for (int i = tid; i < Fq * NFq; i += 512) {   // Wt[n][k]
        int k = i >> 7, n = i & 127;
        float v = (k < Pq) ? Wout[k * NFq + n]
                           : g_M[(long)b * Aq * NFq + (k - Pq) * NFq + n];
        Wt[n * XS3 + k] = f2tf32(v);
    }
    if (tid < NFq) bs[tid] = bout[tid];
    __syncthreads();

    const int wid = tid >> 5, lane = tid & 31;
    const int wm = wid >> 2, wn = wid & 3;     // 4 x 4 warps, m32 x n32 tiles
    const int lq = lane & 3, lg = lane >> 2;

    const int rA = lane & 15;
    const int cA = (lane & 16) >> 2;
    const int rB = (lane & 7) + ((lane & 16) >> 1);
    const int cB = (lane & 8) >> 1;

    uint32_t aAddr[2], bAddr[2];
#pragma unroll
    for (int mt = 0; mt < 2; mt++)
        aAddr[mt] = s2u(Xs + (wm * 32 + mt * 16 + rA) * XS3 + cA);
#pragma unroll
    for (int p = 0; p < 2; p++)
        bAddr[p] = s2u(Wt + (wn * 32 + p * 16 + rB) * XS3 + cB);

    float d[2][4][4];
#pragma unroll
    for (int mt = 0; mt < 2; mt++)
#pragma unroll
        for (int nt = 0; nt < 4; nt++)
#pragma unroll
            for (int r = 0; r < 4; r++) d[mt][nt][r] = 0.f;

#pragma unroll
    for (int ks = 0; ks < 9; ks++) {
        uint32_t a[2][4];
#pragma unroll
        for (int mt = 0; mt < 2; mt++) {
            ldsm4(a[mt], aAddr[mt]); aAddr[mt] += 32;
        }
        uint32_t bf[4][2];
#pragma unroll
        for (int p = 0; p < 2; p++) {
            ldsm4(&bf[2 * p][0], bAddr[p]); bAddr[p] += 32;
        }
#pragma unroll
        for (int mt = 0; mt < 2; mt++)
#pragma unroll
            for (int nt = 0; nt < 4; nt++)
                mma_tf32(d[mt][nt], a[mt], bf[nt]);
    }

#pragma unroll
    for (int mt = 0; mt < 2; mt++) {
        const long r0 = row0 + wm * 32 + mt * 16 + lg;
#pragma unroll
        for (int nt = 0; nt < 4; nt++) {
            const int c0 = wn * 32 + nt * 8 + 2 * lq;
            float2 o0, o1;
            o0.x = ftanh(d[mt][nt][0] + bs[c0]);
            o0.y = ftanh(d[mt][nt][1] + bs[c0 + 1]);
            o1.x = ftanh(d[mt][nt][2] + bs[c0]);
            o1.y = ftanh(d[mt][nt][3] + bs[c0 + 1]);
            *(float2*)(out + (r0)     * NFq + c0) = o0;
            *(float2*)(out + (r0 + 8) * NFq + c0) = o1;
        }
    }
}

// ---------------------------------------------------------------------------
extern "C" void kernel_launch(void* const* d_in, const int* in_sizes, int n_in,
                              void* d_out, int out_size) {
    const float* X    = (const float*)d_in[0];
    const float* W1   = (const float*)d_in[1];
    const float* b1   = (const float*)d_in[2];
    const float* W2   = (const float*)d_in[3];
    const float* b2   = (const float*)d_in[4];
    const float* Wout = (const float*)d_in[5];
    const float* bout = (const float*)d_in[6];
    float* out = (float*)d_out;

    const int smem1 = (Fq * XS1 + 128 * SFS) * 4 + Fq * 4;     // ~60.8 KB
    const int smem3 = (128 * XS3 * 2) * 4 + NFq * 4;           // ~78.3 KB
    cudaFuncSetAttribute(k1, cudaFuncAttributeMaxDynamicSharedMemorySize, smem1);
    cudaFuncSetAttribute(k3, cudaFuncAttributeMaxDynamicSharedMemorySize, smem3);

    k1<<<(Bq * Vq) / 128, 576, smem1>>>(X, W1, b1, W2, b2);

    kB2<<<Bq, 576>>>(Wout);

    k3<<<(Bq * Vq) / 128, 512, smem3>>>(X, Wout, bout, out);
}